// round 1
// baseline (speedup 1.0000x reference)
#include <cuda_runtime.h>
#include <math.h>

// ---------------- problem constants ----------------
#define HDIM   512
#define HEADS  16
#define HD     32          // head dim
#define WS     8
#define L      64          // WS*WS
#define NW     1024        // (256/8)^2 windows
#define NTOK   65536       // NW * L
#define IMG    256
#define NPIX   65536       // 256*256

// ---------------- scratch (device globals; no allocation allowed) ----------
__device__ float g_win[(size_t)NTOK * HDIM];       // windowed input (residual 1)
__device__ float g_xn[(size_t)NTOK * HDIM];        // LN output (reused)
__device__ float g_qkv[(size_t)NTOK * 3 * HDIM];   // qkv
__device__ float g_att[(size_t)NTOK * HDIM];       // attention out
__device__ float g_o1[(size_t)NTOK * HDIM];        // residual 1 out
__device__ float g_h[(size_t)NTOK * 4 * HDIM];     // mlp hidden

// ---------------- kernel 1: roll + window partition (C,H,W)->(token,C) -----
__global__ void partition_kernel(const float* __restrict__ x, float* __restrict__ win)
{
    __shared__ float tile[32][33];     // tile[channel][token]
    int t0 = blockIdx.x * 32;
    int c0 = blockIdx.y * 32;
    int tx = threadIdx.x;              // 0..31
    int ty = threadIdx.y;              // 0..7

    // source pixel for token t0+tx
    int t  = t0 + tx;
    int w  = t >> 6;
    int l  = t & 63;
    int hb = w >> 5, wb = w & 31;
    int ii = l >> 3, jj = l & 7;
    int sh = (hb * 8 + ii + 4) & 255;  // roll(-4)
    int sw = (wb * 8 + jj + 4) & 255;
    int pix = sh * IMG + sw;

#pragma unroll
    for (int cc = 0; cc < 4; cc++) {
        int c = c0 + ty + cc * 8;
        tile[ty + cc * 8][tx] = x[(size_t)c * NPIX + pix];
    }
    __syncthreads();
#pragma unroll
    for (int cc = 0; cc < 4; cc++) {
        int tt = ty + cc * 8;
        win[(size_t)(t0 + tt) * HDIM + c0 + tx] = tile[tx][tt];
    }
}

// ---------------- kernel 9: window reverse + roll back ---------------------
__global__ void reverse_kernel(const float* __restrict__ o2, float* __restrict__ out)
{
    __shared__ float tile[32][33];     // tile[token][channel]
    int t0 = blockIdx.x * 32;
    int c0 = blockIdx.y * 32;
    int tx = threadIdx.x;
    int ty = threadIdx.y;

#pragma unroll
    for (int cc = 0; cc < 4; cc++) {
        int tt = ty + cc * 8;
        tile[tt][tx] = o2[(size_t)(t0 + tt) * HDIM + c0 + tx];
    }
    __syncthreads();

    int t  = t0 + tx;
    int w  = t >> 6;
    int l  = t & 63;
    int hb = w >> 5, wb = w & 31;
    int ii = l >> 3, jj = l & 7;
    int dh = (hb * 8 + ii + 4) & 255;  // roll(+4) of reversed image == same map
    int dw = (wb * 8 + jj + 4) & 255;
    int pix = dh * IMG + dw;

#pragma unroll
    for (int cc = 0; cc < 4; cc++) {
        int c = c0 + ty + cc * 8;
        out[(size_t)c * NPIX + pix] = tile[tx][ty + cc * 8];
    }
}

// ---------------- LayerNorm (warp per token, C=512) ------------------------
__global__ void ln_kernel(const float* __restrict__ in, float* __restrict__ out,
                          const float* __restrict__ w, const float* __restrict__ b)
{
    int warp = (blockIdx.x * blockDim.x + threadIdx.x) >> 5;
    int lane = threadIdx.x & 31;
    if (warp >= NTOK) return;
    const float* row = in + (size_t)warp * HDIM;

    float4 v[4];
    float sum = 0.f, sq = 0.f;
#pragma unroll
    for (int i = 0; i < 4; i++) {
        v[i] = *(const float4*)(row + (size_t)(i * 32 + lane) * 4);
        sum += v[i].x + v[i].y + v[i].z + v[i].w;
        sq  += v[i].x * v[i].x + v[i].y * v[i].y + v[i].z * v[i].z + v[i].w * v[i].w;
    }
#pragma unroll
    for (int o = 16; o; o >>= 1) {
        sum += __shfl_xor_sync(0xffffffffu, sum, o);
        sq  += __shfl_xor_sync(0xffffffffu, sq, o);
    }
    float mu  = sum * (1.f / HDIM);
    float var = sq * (1.f / HDIM) - mu * mu;
    float inv = rsqrtf(var + 1e-5f);

    float* orow = out + (size_t)warp * HDIM;
#pragma unroll
    for (int i = 0; i < 4; i++) {
        int c = (i * 32 + lane) * 4;
        float4 wv = *(const float4*)(w + c);
        float4 bv = *(const float4*)(b + c);
        float4 r;
        r.x = (v[i].x - mu) * inv * wv.x + bv.x;
        r.y = (v[i].y - mu) * inv * wv.y + bv.y;
        r.z = (v[i].z - mu) * inv * wv.z + bv.z;
        r.w = (v[i].w - mu) * inv * wv.w + bv.w;
        *(float4*)(orow + c) = r;
    }
}

// ---------------- tiled SGEMM with fused epilogues -------------------------
// C[M,N] = epi(A[M,K] @ B[K,N] + bias)
// EPI 0: +bias   1: +bias then exact GELU   2: res + gamma*(+bias)
#define BM 64
#define BN 64
#define BKK 16

template <int EPI>
__global__ void sgemm_kernel(const float* __restrict__ A, const float* __restrict__ B,
                             const float* __restrict__ bias, float* __restrict__ C,
                             int M, int N, int K,
                             const float* __restrict__ res, const float* __restrict__ gamma)
{
    __shared__ float As[BKK][BM];
    __shared__ float Bs[BKK][BN];

    int bx = blockIdx.x;              // N tile
    int by = blockIdx.y;              // M tile
    int tid = threadIdx.x;            // 256
    int tx = tid & 15;                // 0..15 col group
    int ty = tid >> 4;                // 0..15 row group
    int row0 = by * BM;
    int col0 = bx * BN;

    int ar = tid >> 2;                // 0..63
    int ac = (tid & 3) * 4;           // 0,4,8,12
    int br = tid >> 4;                // 0..15
    int bc = (tid & 15) * 4;          // 0..60

    const float* Aptr = A + (size_t)(row0 + ar) * K;
    const float* Bptr = B + (size_t)br * N + col0 + bc;

    float acc[4][4] = {};

    for (int k0 = 0; k0 < K; k0 += BKK) {
        float4 a4 = *(const float4*)(Aptr + k0 + ac);
        float4 b4 = *(const float4*)(Bptr + (size_t)k0 * N);
        __syncthreads();
        As[ac + 0][ar] = a4.x;
        As[ac + 1][ar] = a4.y;
        As[ac + 2][ar] = a4.z;
        As[ac + 3][ar] = a4.w;
        *(float4*)&Bs[br][bc] = b4;
        __syncthreads();
#pragma unroll
        for (int kk = 0; kk < BKK; kk++) {
            float4 av = *(const float4*)&As[kk][ty * 4];
            float4 bv = *(const float4*)&Bs[kk][tx * 4];
            acc[0][0] += av.x * bv.x; acc[0][1] += av.x * bv.y; acc[0][2] += av.x * bv.z; acc[0][3] += av.x * bv.w;
            acc[1][0] += av.y * bv.x; acc[1][1] += av.y * bv.y; acc[1][2] += av.y * bv.z; acc[1][3] += av.y * bv.w;
            acc[2][0] += av.z * bv.x; acc[2][1] += av.z * bv.y; acc[2][2] += av.z * bv.z; acc[2][3] += av.z * bv.w;
            acc[3][0] += av.w * bv.x; acc[3][1] += av.w * bv.y; acc[3][2] += av.w * bv.z; acc[3][3] += av.w * bv.w;
        }
    }

    int cbase = col0 + tx * 4;
    float4 bb = *(const float4*)(bias + cbase);
    float4 gg = make_float4(0.f, 0.f, 0.f, 0.f);
    if (EPI == 2) gg = *(const float4*)(gamma + cbase);

#pragma unroll
    for (int i = 0; i < 4; i++) {
        int r = row0 + ty * 4 + i;
        float4 v;
        v.x = acc[i][0] + bb.x;
        v.y = acc[i][1] + bb.y;
        v.z = acc[i][2] + bb.z;
        v.w = acc[i][3] + bb.w;
        if (EPI == 1) {
            v.x = 0.5f * v.x * (1.f + erff(v.x * 0.70710678118f));
            v.y = 0.5f * v.y * (1.f + erff(v.y * 0.70710678118f));
            v.z = 0.5f * v.z * (1.f + erff(v.z * 0.70710678118f));
            v.w = 0.5f * v.w * (1.f + erff(v.w * 0.70710678118f));
        }
        if (EPI == 2) {
            float4 rv = *(const float4*)(res + (size_t)r * N + cbase);
            v.x = rv.x + gg.x * v.x;
            v.y = rv.y + gg.y * v.y;
            v.z = rv.z + gg.z * v.z;
            v.w = rv.w + gg.w * v.w;
        }
        *(float4*)(C + (size_t)r * N + cbase) = v;
    }
}

// ---------------- attention: one block per (window, head) ------------------
__global__ void attn_kernel(const float* __restrict__ qkv,
                            const float* __restrict__ rel_table,
                            float* __restrict__ out)
{
    __shared__ float qs[L][33], ks[L][33], vs[L][33];
    __shared__ float ss[L][65];
    __shared__ float tbl[225];
    __shared__ int   rg[L];

    int w = blockIdx.x;   // window
    int h = blockIdx.y;   // head
    int tid = threadIdx.x;

    for (int i = tid; i < 225; i += 256) tbl[i] = rel_table[i * HEADS + h];

    if (tid < 64) {
        int hb = w >> 5, wb = w & 31;
        int ii = hb * 8 + (tid >> 3);
        int jj = wb * 8 + (tid & 7);
        int rh = (ii < 248) ? 0 : (ii < 252 ? 1 : 2);
        int rw = (jj < 248) ? 0 : (jj < 252 ? 1 : 2);
        rg[tid] = rh * 3 + rw;
    }

    const float* base = qkv + (size_t)w * L * (3 * HDIM) + h * HD;
    for (int e = tid; e < L * HD; e += 256) {
        int l = e >> 5;
        int d = e & 31;
        const float* p = base + (size_t)l * (3 * HDIM);
        qs[l][d] = p[d];
        ks[l][d] = p[HDIM + d];
        vs[l][d] = p[2 * HDIM + d];
    }
    __syncthreads();

    int l    = tid >> 2;          // 0..63
    int seg  = tid & 3;
    int mseg = seg * 16;
    int il = l >> 3, jl = l & 7;
    int myrg = rg[l];
    const float scale = 0.17677669529663687f;  // 1/sqrt(32)

    float qr[HD];
#pragma unroll
    for (int d = 0; d < HD; d++) qr[d] = qs[l][d];

    float sv[16];
#pragma unroll
    for (int mm = 0; mm < 16; mm++) {
        int m = mseg + mm;
        float a = 0.f;
#pragma unroll
        for (int d = 0; d < HD; d++) a += qr[d] * ks[m][d];
        int im = m >> 3, jm = m & 7;
        int ridx = (il - im + 7) * 15 + (jl - jm + 7);
        float val = a * scale + tbl[ridx];
        if (rg[m] != myrg) val = -1e30f;
        sv[mm] = val;
    }

    // softmax across the 4 lanes owning this row (consecutive lane ids)
    float mx = sv[0];
#pragma unroll
    for (int mm = 1; mm < 16; mm++) mx = fmaxf(mx, sv[mm]);
    mx = fmaxf(mx, __shfl_xor_sync(0xffffffffu, mx, 1));
    mx = fmaxf(mx, __shfl_xor_sync(0xffffffffu, mx, 2));
    float sum = 0.f;
#pragma unroll
    for (int mm = 0; mm < 16; mm++) { sv[mm] = __expf(sv[mm] - mx); sum += sv[mm]; }
    sum += __shfl_xor_sync(0xffffffffu, sum, 1);
    sum += __shfl_xor_sync(0xffffffffu, sum, 2);
    float inv = 1.f / sum;
#pragma unroll
    for (int mm = 0; mm < 16; mm++) ss[l][mseg + mm] = sv[mm] * inv;
    __syncthreads();

    // O = P @ V : each thread 8 output dims of its row
    int dseg = seg * 8;
    float o[8] = {};
#pragma unroll 8
    for (int m = 0; m < L; m++) {
        float p = ss[l][m];
#pragma unroll
        for (int dd = 0; dd < 8; dd++) o[dd] += p * vs[m][dseg + dd];
    }
    float* op = out + (size_t)(w * L + l) * HDIM + h * HD + dseg;
#pragma unroll
    for (int dd = 0; dd < 8; dd++) op[dd] = o[dd];
}

// ---------------- launch -----------------------------------------------------
extern "C" void kernel_launch(void* const* d_in, const int* in_sizes, int n_in,
                              void* d_out, int out_size)
{
    (void)in_sizes; (void)n_in; (void)out_size;
    const float* x     = (const float*)d_in[0];
    const float* n1w   = (const float*)d_in[1];
    const float* n1b   = (const float*)d_in[2];
    const float* qkvw  = (const float*)d_in[3];
    const float* qkvb  = (const float*)d_in[4];
    const float* projw = (const float*)d_in[5];
    const float* projb = (const float*)d_in[6];
    const float* relt  = (const float*)d_in[7];
    const float* g1    = (const float*)d_in[8];
    const float* n2w   = (const float*)d_in[9];
    const float* n2b   = (const float*)d_in[10];
    const float* fc1w  = (const float*)d_in[11];
    const float* fc1b  = (const float*)d_in[12];
    const float* fc2w  = (const float*)d_in[13];
    const float* fc2b  = (const float*)d_in[14];
    const float* g2    = (const float*)d_in[15];
    float* out = (float*)d_out;

    float *p_win, *p_xn, *p_qkv, *p_att, *p_o1, *p_h;
    cudaGetSymbolAddress((void**)&p_win, g_win);
    cudaGetSymbolAddress((void**)&p_xn,  g_xn);
    cudaGetSymbolAddress((void**)&p_qkv, g_qkv);
    cudaGetSymbolAddress((void**)&p_att, g_att);
    cudaGetSymbolAddress((void**)&p_o1,  g_o1);
    cudaGetSymbolAddress((void**)&p_h,   g_h);

    dim3 tp(32, 8);
    // 1. roll + partition
    partition_kernel<<<dim3(NTOK / 32, HDIM / 32), tp>>>(x, p_win);
    // 2. LN1
    ln_kernel<<<NTOK / 8, 256>>>(p_win, p_xn, n1w, n1b);
    // 3. QKV gemm
    sgemm_kernel<0><<<dim3((3 * HDIM) / BN, NTOK / BM), 256>>>(
        p_xn, qkvw, qkvb, p_qkv, NTOK, 3 * HDIM, HDIM, nullptr, nullptr);
    // 4. windowed attention
    attn_kernel<<<dim3(NW, HEADS), 256>>>(p_qkv, relt, p_att);
    // 5. proj gemm + residual (o1 = win + g1*(att@W+b))
    sgemm_kernel<2><<<dim3(HDIM / BN, NTOK / BM), 256>>>(
        p_att, projw, projb, p_o1, NTOK, HDIM, HDIM, p_win, g1);
    // 6. LN2
    ln_kernel<<<NTOK / 8, 256>>>(p_o1, p_xn, n2w, n2b);
    // 7. fc1 + GELU
    sgemm_kernel<1><<<dim3((4 * HDIM) / BN, NTOK / BM), 256>>>(
        p_xn, fc1w, fc1b, p_h, NTOK, 4 * HDIM, HDIM, nullptr, nullptr);
    // 8. fc2 + residual (o2 = o1 + g2*(h@W+b)), reuse g_win as o2
    sgemm_kernel<2><<<dim3(HDIM / BN, NTOK / BM), 256>>>(
        p_h, fc2w, fc2b, p_win, NTOK, HDIM, 4 * HDIM, p_o1, g2);
    // 9. reverse + roll back
    reverse_kernel<<<dim3(NTOK / 32, HDIM / 32), tp>>>(p_win, out);
}

// round 3
// speedup vs baseline: 3.8729x; 3.8729x over previous
#include <cuda_runtime.h>
#include <cuda_bf16.h>
#include <stdint.h>
#include <math.h>

// ---------------- problem constants ----------------
#define HDIM   512
#define HEADS  16
#define HD     32          // head dim
#define WS     8
#define L      64          // WS*WS
#define NW     1024        // (256/8)^2 windows
#define NTOK   65536       // NW * L
#define IMG    256
#define NPIX   65536       // 256*256

typedef __nv_bfloat16 bf16;
typedef __nv_bfloat162 bf162;

// ---------------- scratch (device globals; no allocation allowed) ----------
__device__ float g_win[(size_t)NTOK * HDIM];        // windowed input (residual 1)
__device__ float g_qkv[(size_t)NTOK * 3 * HDIM];    // qkv (fp32 for attention)
__device__ float g_o1[(size_t)NTOK * HDIM];         // residual 1 out
__device__ bf16  g_xnb[(size_t)NTOK * HDIM];        // LN output bf16
__device__ bf16  g_attb[(size_t)NTOK * HDIM];       // attention out bf16
__device__ bf16  g_hb[(size_t)NTOK * 4 * HDIM];     // mlp hidden bf16
__device__ bf16  g_wq[(size_t)HDIM * 3 * HDIM];     // weights bf16
__device__ bf16  g_wp[(size_t)HDIM * HDIM];
__device__ bf16  g_w1[(size_t)HDIM * 4 * HDIM];
__device__ bf16  g_w2[(size_t)4 * HDIM * HDIM];

// ---------------- fp32 -> bf16 conversion ----------------------------------
__global__ void f2bf_kernel(const float* __restrict__ in, bf16* __restrict__ out, int n4)
{
    int i = blockIdx.x * blockDim.x + threadIdx.x;
    if (i >= n4) return;
    float4 v = *(const float4*)(in + (size_t)i * 4);
    bf162 lo = __floats2bfloat162_rn(v.x, v.y);
    bf162 hi = __floats2bfloat162_rn(v.z, v.w);
    *(bf162*)(out + (size_t)i * 4)     = lo;
    *(bf162*)(out + (size_t)i * 4 + 2) = hi;
}

// ---------------- kernel 1: roll + window partition (C,H,W)->(token,C) -----
__global__ void partition_kernel(const float* __restrict__ x, float* __restrict__ win)
{
    __shared__ float tile[32][33];
    int t0 = blockIdx.x * 32;
    int c0 = blockIdx.y * 32;
    int tx = threadIdx.x;
    int ty = threadIdx.y;

    int t  = t0 + tx;
    int w  = t >> 6;
    int l  = t & 63;
    int hb = w >> 5, wb = w & 31;
    int ii = l >> 3, jj = l & 7;
    int sh = (hb * 8 + ii + 4) & 255;
    int sw = (wb * 8 + jj + 4) & 255;
    int pix = sh * IMG + sw;

#pragma unroll
    for (int cc = 0; cc < 4; cc++) {
        int c = c0 + ty + cc * 8;
        tile[ty + cc * 8][tx] = x[(size_t)c * NPIX + pix];
    }
    __syncthreads();
#pragma unroll
    for (int cc = 0; cc < 4; cc++) {
        int tt = ty + cc * 8;
        win[(size_t)(t0 + tt) * HDIM + c0 + tx] = tile[tx][tt];
    }
}

// ---------------- window reverse + roll back -------------------------------
__global__ void reverse_kernel(const float* __restrict__ o2, float* __restrict__ out)
{
    __shared__ float tile[32][33];
    int t0 = blockIdx.x * 32;
    int c0 = blockIdx.y * 32;
    int tx = threadIdx.x;
    int ty = threadIdx.y;

#pragma unroll
    for (int cc = 0; cc < 4; cc++) {
        int tt = ty + cc * 8;
        tile[tt][tx] = o2[(size_t)(t0 + tt) * HDIM + c0 + tx];
    }
    __syncthreads();

    int t  = t0 + tx;
    int w  = t >> 6;
    int l  = t & 63;
    int hb = w >> 5, wb = w & 31;
    int ii = l >> 3, jj = l & 7;
    int dh = (hb * 8 + ii + 4) & 255;
    int dw = (wb * 8 + jj + 4) & 255;
    int pix = dh * IMG + dw;

#pragma unroll
    for (int cc = 0; cc < 4; cc++) {
        int c = c0 + ty + cc * 8;
        out[(size_t)c * NPIX + pix] = tile[tx][ty + cc * 8];
    }
}

// ---------------- LayerNorm (warp per token, C=512), bf16 out --------------
__global__ void ln_kernel(const float* __restrict__ in, bf16* __restrict__ out,
                          const float* __restrict__ w, const float* __restrict__ b)
{
    int warp = (blockIdx.x * blockDim.x + threadIdx.x) >> 5;
    int lane = threadIdx.x & 31;
    if (warp >= NTOK) return;
    const float* row = in + (size_t)warp * HDIM;

    float4 v[4];
    float sum = 0.f, sq = 0.f;
#pragma unroll
    for (int i = 0; i < 4; i++) {
        v[i] = *(const float4*)(row + (size_t)(i * 32 + lane) * 4);
        sum += v[i].x + v[i].y + v[i].z + v[i].w;
        sq  += v[i].x * v[i].x + v[i].y * v[i].y + v[i].z * v[i].z + v[i].w * v[i].w;
    }
#pragma unroll
    for (int o = 16; o; o >>= 1) {
        sum += __shfl_xor_sync(0xffffffffu, sum, o);
        sq  += __shfl_xor_sync(0xffffffffu, sq, o);
    }
    float mu  = sum * (1.f / HDIM);
    float var = sq * (1.f / HDIM) - mu * mu;
    float inv = rsqrtf(var + 1e-5f);

    bf16* orow = out + (size_t)warp * HDIM;
#pragma unroll
    for (int i = 0; i < 4; i++) {
        int c = (i * 32 + lane) * 4;
        float4 wv = *(const float4*)(w + c);
        float4 bv = *(const float4*)(b + c);
        float rx = (v[i].x - mu) * inv * wv.x + bv.x;
        float ry = (v[i].y - mu) * inv * wv.y + bv.y;
        float rz = (v[i].z - mu) * inv * wv.z + bv.z;
        float rw = (v[i].w - mu) * inv * wv.w + bv.w;
        *(bf162*)(orow + c)     = __floats2bfloat162_rn(rx, ry);
        *(bf162*)(orow + c + 2) = __floats2bfloat162_rn(rz, rw);
    }
}

// ---------------- bf16 tensor-core GEMM with fused epilogues ---------------
// C[M,N] = epi(A[M,K] @ B[K,N] + bias)
// EPI 0: +bias (fp32 out)   1: +bias -> exact GELU (bf16 out)
// EPI 2: res + gamma*(+bias) (fp32 out)
#define GBM 128
#define GBN 128
#define GBK 32

#define CP_ASYNC16(dst, src) \
    asm volatile("cp.async.cg.shared.global [%0], [%1], 16;\n" :: "r"(dst), "l"(src))

template <int EPI, typename CT>
__global__ void __launch_bounds__(256) bgemm_kernel(
    const bf16* __restrict__ A, const bf16* __restrict__ B,
    const float* __restrict__ bias, CT* __restrict__ C,
    int M, int N, int K,
    const float* __restrict__ res, const float* __restrict__ gamma)
{
    __shared__ bf16 As[2][GBM][GBK + 8];   // 128 x 40
    __shared__ bf16 Bs[2][GBK][GBN + 8];   // 32 x 136

    int tid  = threadIdx.x;
    int lane = tid & 31;
    int warp = tid >> 5;
    int wm = warp >> 2;      // 0..1
    int wn = warp & 3;       // 0..3
    int row0 = blockIdx.y * GBM;
    int col0 = blockIdx.x * GBN;

    const bf16* Ab = A + (size_t)row0 * K;
    const bf16* Bb = B + col0;

    // per-thread load coords (2 chunks of 16B each for A and B)
    int a_r[2], a_c[2], b_r[2], b_c[2];
#pragma unroll
    for (int i = 0; i < 2; i++) {
        int ch = tid * 2 + i;          // 0..511
        a_r[i] = ch >> 2;  a_c[i] = (ch & 3) * 8;
        b_r[i] = ch >> 4;  b_c[i] = (ch & 15) * 8;
    }

    float acc[4][4][4];
#pragma unroll
    for (int mi = 0; mi < 4; mi++)
#pragma unroll
        for (int ni = 0; ni < 4; ni++)
#pragma unroll
            for (int r = 0; r < 4; r++) acc[mi][ni][r] = 0.f;

    // prologue load tile 0
    {
#pragma unroll
        for (int i = 0; i < 2; i++) {
            unsigned dst = (unsigned)__cvta_generic_to_shared(&As[0][a_r[i]][a_c[i]]);
            CP_ASYNC16(dst, Ab + (size_t)a_r[i] * K + a_c[i]);
        }
#pragma unroll
        for (int i = 0; i < 2; i++) {
            unsigned dst = (unsigned)__cvta_generic_to_shared(&Bs[0][b_r[i]][b_c[i]]);
            CP_ASYNC16(dst, Bb + (size_t)b_r[i] * N + b_c[i]);
        }
        asm volatile("cp.async.commit_group;\n" ::: "memory");
    }

    int nk = K / GBK;
    for (int kt = 0; kt < nk; kt++) {
        asm volatile("cp.async.wait_group 0;\n" ::: "memory");
        __syncthreads();
        int cur = kt & 1;
        if (kt + 1 < nk) {
            int k0 = (kt + 1) * GBK;
            int nb = cur ^ 1;
#pragma unroll
            for (int i = 0; i < 2; i++) {
                unsigned dst = (unsigned)__cvta_generic_to_shared(&As[nb][a_r[i]][a_c[i]]);
                CP_ASYNC16(dst, Ab + (size_t)a_r[i] * K + k0 + a_c[i]);
            }
#pragma unroll
            for (int i = 0; i < 2; i++) {
                unsigned dst = (unsigned)__cvta_generic_to_shared(&Bs[nb][b_r[i]][b_c[i]]);
                CP_ASYNC16(dst, Bb + (size_t)(k0 + b_r[i]) * N + b_c[i]);
            }
            asm volatile("cp.async.commit_group;\n" ::: "memory");
        }

#pragma unroll
        for (int kk = 0; kk < 2; kk++) {
            unsigned a[4][4], b[4][2];
#pragma unroll
            for (int mi = 0; mi < 4; mi++) {
                unsigned addr = (unsigned)__cvta_generic_to_shared(
                    &As[cur][wm * 64 + mi * 16 + (lane & 15)][kk * 16 + (lane >> 4) * 8]);
                asm volatile("ldmatrix.sync.aligned.m8n8.x4.shared.b16 {%0,%1,%2,%3},[%4];"
                    : "=r"(a[mi][0]), "=r"(a[mi][1]), "=r"(a[mi][2]), "=r"(a[mi][3])
                    : "r"(addr));
            }
#pragma unroll
            for (int ni = 0; ni < 4; ni++) {
                unsigned addr = (unsigned)__cvta_generic_to_shared(
                    &Bs[cur][kk * 16 + (lane & 15)][wn * 32 + ni * 8]);
                asm volatile("ldmatrix.sync.aligned.m8n8.x2.trans.shared.b16 {%0,%1},[%2];"
                    : "=r"(b[ni][0]), "=r"(b[ni][1]) : "r"(addr));
            }
#pragma unroll
            for (int mi = 0; mi < 4; mi++)
#pragma unroll
                for (int ni = 0; ni < 4; ni++)
                    asm volatile("mma.sync.aligned.m16n8k16.row.col.f32.bf16.bf16.f32 "
                        "{%0,%1,%2,%3},{%4,%5,%6,%7},{%8,%9},{%0,%1,%2,%3};"
                        : "+f"(acc[mi][ni][0]), "+f"(acc[mi][ni][1]),
                          "+f"(acc[mi][ni][2]), "+f"(acc[mi][ni][3])
                        : "r"(a[mi][0]), "r"(a[mi][1]), "r"(a[mi][2]), "r"(a[mi][3]),
                          "r"(b[ni][0]), "r"(b[ni][1]));
        }
    }

    // epilogue: lane -> (r = lane>>2, c = (lane&3)*2) within each m16n8 tile
    int lr = lane >> 2;
    int lc = (lane & 3) * 2;
#pragma unroll
    for (int mi = 0; mi < 4; mi++) {
#pragma unroll
        for (int half = 0; half < 2; half++) {
            int grow = row0 + wm * 64 + mi * 16 + lr + half * 8;
#pragma unroll
            for (int ni = 0; ni < 4; ni++) {
                int gcol = col0 + wn * 32 + ni * 8 + lc;
                float v0 = acc[mi][ni][half * 2 + 0] + bias[gcol];
                float v1 = acc[mi][ni][half * 2 + 1] + bias[gcol + 1];
                if (EPI == 1) {
                    v0 = 0.5f * v0 * (1.f + erff(v0 * 0.70710678118f));
                    v1 = 0.5f * v1 * (1.f + erff(v1 * 0.70710678118f));
                }
                if (EPI == 2) {
                    const float* rp = res + (size_t)grow * N + gcol;
                    v0 = rp[0] + gamma[gcol] * v0;
                    v1 = rp[1] + gamma[gcol + 1] * v1;
                }
                if (sizeof(CT) == 4) {
                    float* cp = (float*)C + (size_t)grow * N + gcol;
                    cp[0] = v0; cp[1] = v1;
                } else {
                    bf16* cp = (bf16*)C + (size_t)grow * N + gcol;
                    *(bf162*)cp = __floats2bfloat162_rn(v0, v1);
                }
            }
        }
    }
}

// ---------------- attention: one block per (window, head) ------------------
__global__ void attn_kernel(const float* __restrict__ qkv,
                            const float* __restrict__ rel_table,
                            bf16* __restrict__ out)
{
    __shared__ float qs[L][33], ks[L][33], vs[L][33];
    __shared__ float ss[L][65];
    __shared__ float tbl[225];
    __shared__ int   rg[L];

    int w = blockIdx.x;
    int h = blockIdx.y;
    int tid = threadIdx.x;

    for (int i = tid; i < 225; i += 256) tbl[i] = rel_table[i * HEADS + h];

    if (tid < 64) {
        int hb = w >> 5, wb = w & 31;
        int ii = hb * 8 + (tid >> 3);
        int jj = wb * 8 + (tid & 7);
        int rh = (ii < 248) ? 0 : (ii < 252 ? 1 : 2);
        int rw = (jj < 248) ? 0 : (jj < 252 ? 1 : 2);
        rg[tid] = rh * 3 + rw;
    }

    const float* base = qkv + (size_t)w * L * (3 * HDIM) + h * HD;
    for (int e = tid; e < L * HD; e += 256) {
        int l = e >> 5;
        int d = e & 31;
        const float* p = base + (size_t)l * (3 * HDIM);
        qs[l][d] = p[d];
        ks[l][d] = p[HDIM + d];
        vs[l][d] = p[2 * HDIM + d];
    }
    __syncthreads();

    int l    = tid >> 2;
    int seg  = tid & 3;
    int mseg = seg * 16;
    int il = l >> 3, jl = l & 7;
    int myrg = rg[l];
    const float scale = 0.17677669529663687f;

    float qr[HD];
#pragma unroll
    for (int d = 0; d < HD; d++) qr[d] = qs[l][d];

    float sv[16];
#pragma unroll
    for (int mm = 0; mm < 16; mm++) {
        int m = mseg + mm;
        float a = 0.f;
#pragma unroll
        for (int d = 0; d < HD; d++) a += qr[d] * ks[m][d];
        int im = m >> 3, jm = m & 7;
        int ridx = (il - im + 7) * 15 + (jl - jm + 7);
        float val = a * scale + tbl[ridx];
        if (rg[m] != myrg) val = -1e30f;
        sv[mm] = val;
    }

    float mx = sv[0];
#pragma unroll
    for (int mm = 1; mm < 16; mm++) mx = fmaxf(mx, sv[mm]);
    mx = fmaxf(mx, __shfl_xor_sync(0xffffffffu, mx, 1));
    mx = fmaxf(mx, __shfl_xor_sync(0xffffffffu, mx, 2));
    float sum = 0.f;
#pragma unroll
    for (int mm = 0; mm < 16; mm++) { sv[mm] = __expf(sv[mm] - mx); sum += sv[mm]; }
    sum += __shfl_xor_sync(0xffffffffu, sum, 1);
    sum += __shfl_xor_sync(0xffffffffu, sum, 2);
    float inv = 1.f / sum;
#pragma unroll
    for (int mm = 0; mm < 16; mm++) ss[l][mseg + mm] = sv[mm] * inv;
    __syncthreads();

    int dseg = seg * 8;
    float o[8] = {};
#pragma unroll 8
    for (int m = 0; m < L; m++) {
        float p = ss[l][m];
#pragma unroll
        for (int dd = 0; dd < 8; dd++) o[dd] += p * vs[m][dseg + dd];
    }
    bf16* op = out + (size_t)(w * L + l) * HDIM + h * HD + dseg;
#pragma unroll
    for (int dd = 0; dd < 8; dd += 2)
        *(bf162*)(op + dd) = __floats2bfloat162_rn(o[dd], o[dd + 1]);
}

// ---------------- launch -----------------------------------------------------
extern "C" void kernel_launch(void* const* d_in, const int* in_sizes, int n_in,
                              void* d_out, int out_size)
{
    (void)in_sizes; (void)n_in; (void)out_size;
    const float* x     = (const float*)d_in[0];
    const float* n1w   = (const float*)d_in[1];
    const float* n1b   = (const float*)d_in[2];
    const float* qkvw  = (const float*)d_in[3];
    const float* qkvb  = (const float*)d_in[4];
    const float* projw = (const float*)d_in[5];
    const float* projb = (const float*)d_in[6];
    const float* relt  = (const float*)d_in[7];
    const float* g1    = (const float*)d_in[8];
    const float* n2w   = (const float*)d_in[9];
    const float* n2b   = (const float*)d_in[10];
    const float* fc1w  = (const float*)d_in[11];
    const float* fc1b  = (const float*)d_in[12];
    const float* fc2w  = (const float*)d_in[13];
    const float* fc2b  = (const float*)d_in[14];
    const float* g2    = (const float*)d_in[15];
    float* out = (float*)d_out;

    float *p_win, *p_qkv, *p_o1;
    bf16 *p_xnb, *p_attb, *p_hb, *p_wq, *p_wp, *p_w1, *p_w2;
    cudaGetSymbolAddress((void**)&p_win,  g_win);
    cudaGetSymbolAddress((void**)&p_qkv,  g_qkv);
    cudaGetSymbolAddress((void**)&p_o1,   g_o1);
    cudaGetSymbolAddress((void**)&p_xnb,  g_xnb);
    cudaGetSymbolAddress((void**)&p_attb, g_attb);
    cudaGetSymbolAddress((void**)&p_hb,   g_hb);
    cudaGetSymbolAddress((void**)&p_wq,   g_wq);
    cudaGetSymbolAddress((void**)&p_wp,   g_wp);
    cudaGetSymbolAddress((void**)&p_w1,   g_w1);
    cudaGetSymbolAddress((void**)&p_w2,   g_w2);

    // weight conversion (cheap; every launch)
    f2bf_kernel<<<(HDIM * 3 * HDIM / 4 + 255) / 256, 256>>>(qkvw, p_wq, HDIM * 3 * HDIM / 4);
    f2bf_kernel<<<(HDIM * HDIM / 4 + 255) / 256, 256>>>(projw, p_wp, HDIM * HDIM / 4);
    f2bf_kernel<<<(HDIM * 4 * HDIM / 4 + 255) / 256, 256>>>(fc1w, p_w1, HDIM * 4 * HDIM / 4);
    f2bf_kernel<<<(4 * HDIM * HDIM / 4 + 255) / 256, 256>>>(fc2w, p_w2, 4 * HDIM * HDIM / 4);

    dim3 tp(32, 8);
    // 1. roll + partition
    partition_kernel<<<dim3(NTOK / 32, HDIM / 32), tp>>>(x, p_win);
    // 2. LN1 -> bf16
    ln_kernel<<<NTOK / 8, 256>>>(p_win, p_xnb, n1w, n1b);
    // 3. QKV gemm (bf16 -> fp32)
    bgemm_kernel<0, float><<<dim3(3 * HDIM / GBN, NTOK / GBM), 256>>>(
        p_xnb, p_wq, qkvb, p_qkv, NTOK, 3 * HDIM, HDIM, nullptr, nullptr);
    // 4. windowed attention -> bf16
    attn_kernel<<<dim3(NW, HEADS), 256>>>(p_qkv, relt, p_attb);
    // 5. proj gemm + residual: o1 = win + g1*(att@W+b)
    bgemm_kernel<2, float><<<dim3(HDIM / GBN, NTOK / GBM), 256>>>(
        p_attb, p_wp, projb, p_o1, NTOK, HDIM, HDIM, p_win, g1);
    // 6. LN2 -> bf16
    ln_kernel<<<NTOK / 8, 256>>>(p_o1, p_xnb, n2w, n2b);
    // 7. fc1 + GELU -> bf16
    bgemm_kernel<1, bf16><<<dim3(4 * HDIM / GBN, NTOK / GBM), 256>>>(
        p_xnb, p_w1, fc1b, p_hb, NTOK, 4 * HDIM, HDIM, nullptr, nullptr);
    // 8. fc2 + residual: o2 = o1 + g2*(h@W+b), into g_win
    bgemm_kernel<2, float><<<dim3(HDIM / GBN, NTOK / GBM), 256>>>(
        p_hb, p_w2, fc2b, p_win, NTOK, HDIM, 4 * HDIM, p_o1, g2);
    // 9. reverse + roll back
    reverse_kernel<<<dim3(NTOK / 32, HDIM / 32), tp>>>(p_win, out);
}

// round 4
// speedup vs baseline: 6.0814x; 1.5702x over previous
#include <cuda_runtime.h>
#include <cuda_bf16.h>
#include <stdint.h>
#include <math.h>

// ---------------- problem constants ----------------
#define HDIM   512
#define HEADS  16
#define HD     32
#define WS     8
#define L      64
#define NW     1024
#define NTOK   65536
#define IMG    256
#define NPIX   65536

typedef __nv_bfloat16 bf16;
typedef __nv_bfloat162 bf162;

// ---------------- scratch ----------------
__device__ float g_win[(size_t)NTOK * HDIM];
__device__ float g_o1[(size_t)NTOK * HDIM];
__device__ __align__(16) bf16 g_xnb[(size_t)NTOK * HDIM];
__device__ __align__(16) bf16 g_qkvb[(size_t)NTOK * 3 * HDIM];
__device__ __align__(16) bf16 g_attb[(size_t)NTOK * HDIM];
__device__ __align__(16) bf16 g_hb[(size_t)NTOK * 4 * HDIM];
__device__ __align__(16) bf16 g_wq[(size_t)HDIM * 3 * HDIM];
__device__ __align__(16) bf16 g_wp[(size_t)HDIM * HDIM];
__device__ __align__(16) bf16 g_w1[(size_t)HDIM * 4 * HDIM];
__device__ __align__(16) bf16 g_w2[(size_t)4 * HDIM * HDIM];

#define CP_ASYNC16(dst, src) \
    asm volatile("cp.async.cg.shared.global [%0], [%1], 16;\n" :: "r"(dst), "l"(src))

__device__ __forceinline__ unsigned sptr(const void* p) {
    return (unsigned)__cvta_generic_to_shared(p);
}
__device__ __forceinline__ unsigned packbf(float x, float y) {
    bf162 t = __floats2bfloat162_rn(x, y);
    return *(unsigned*)&t;
}

// ---------------- fp32 -> bf16 ----------------
__global__ void f2bf_kernel(const float* __restrict__ in, bf16* __restrict__ out, int n4)
{
    int i = blockIdx.x * blockDim.x + threadIdx.x;
    if (i >= n4) return;
    float4 v = *(const float4*)(in + (size_t)i * 4);
    *(bf162*)(out + (size_t)i * 4)     = __floats2bfloat162_rn(v.x, v.y);
    *(bf162*)(out + (size_t)i * 4 + 2) = __floats2bfloat162_rn(v.z, v.w);
}

// ---------------- roll + window partition ----------------
__global__ void partition_kernel(const float* __restrict__ x, float* __restrict__ win)
{
    __shared__ float tile[32][33];
    int t0 = blockIdx.x * 32;
    int c0 = blockIdx.y * 32;
    int tx = threadIdx.x;
    int ty = threadIdx.y;

    int t  = t0 + tx;
    int w  = t >> 6;
    int l  = t & 63;
    int hb = w >> 5, wb = w & 31;
    int ii = l >> 3, jj = l & 7;
    int sh = (hb * 8 + ii + 4) & 255;
    int sw = (wb * 8 + jj + 4) & 255;
    int pix = sh * IMG + sw;

#pragma unroll
    for (int cc = 0; cc < 4; cc++) {
        int c = c0 + ty + cc * 8;
        tile[ty + cc * 8][tx] = x[(size_t)c * NPIX + pix];
    }
    __syncthreads();
#pragma unroll
    for (int cc = 0; cc < 4; cc++) {
        int tt = ty + cc * 8;
        win[(size_t)(t0 + tt) * HDIM + c0 + tx] = tile[tx][tt];
    }
}

// ---------------- window reverse ----------------
__global__ void reverse_kernel(const float* __restrict__ o2, float* __restrict__ out)
{
    __shared__ float tile[32][33];
    int t0 = blockIdx.x * 32;
    int c0 = blockIdx.y * 32;
    int tx = threadIdx.x;
    int ty = threadIdx.y;

#pragma unroll
    for (int cc = 0; cc < 4; cc++) {
        int tt = ty + cc * 8;
        tile[tt][tx] = o2[(size_t)(t0 + tt) * HDIM + c0 + tx];
    }
    __syncthreads();

    int t  = t0 + tx;
    int w  = t >> 6;
    int l  = t & 63;
    int hb = w >> 5, wb = w & 31;
    int ii = l >> 3, jj = l & 7;
    int dh = (hb * 8 + ii + 4) & 255;
    int dw = (wb * 8 + jj + 4) & 255;
    int pix = dh * IMG + dw;

#pragma unroll
    for (int cc = 0; cc < 4; cc++) {
        int c = c0 + ty + cc * 8;
        out[(size_t)c * NPIX + pix] = tile[tx][ty + cc * 8];
    }
}

// ---------------- LayerNorm -> bf16 ----------------
__global__ void ln_kernel(const float* __restrict__ in, bf16* __restrict__ out,
                          const float* __restrict__ w, const float* __restrict__ b)
{
    int warp = (blockIdx.x * blockDim.x + threadIdx.x) >> 5;
    int lane = threadIdx.x & 31;
    if (warp >= NTOK) return;
    const float* row = in + (size_t)warp * HDIM;

    float4 v[4];
    float sum = 0.f, sq = 0.f;
#pragma unroll
    for (int i = 0; i < 4; i++) {
        v[i] = *(const float4*)(row + (size_t)(i * 32 + lane) * 4);
        sum += v[i].x + v[i].y + v[i].z + v[i].w;
        sq  += v[i].x * v[i].x + v[i].y * v[i].y + v[i].z * v[i].z + v[i].w * v[i].w;
    }
#pragma unroll
    for (int o = 16; o; o >>= 1) {
        sum += __shfl_xor_sync(0xffffffffu, sum, o);
        sq  += __shfl_xor_sync(0xffffffffu, sq, o);
    }
    float mu  = sum * (1.f / HDIM);
    float var = sq * (1.f / HDIM) - mu * mu;
    float inv = rsqrtf(var + 1e-5f);

    bf16* orow = out + (size_t)warp * HDIM;
#pragma unroll
    for (int i = 0; i < 4; i++) {
        int c = (i * 32 + lane) * 4;
        float4 wv = *(const float4*)(w + c);
        float4 bv = *(const float4*)(b + c);
        float rx = (v[i].x - mu) * inv * wv.x + bv.x;
        float ry = (v[i].y - mu) * inv * wv.y + bv.y;
        float rz = (v[i].z - mu) * inv * wv.z + bv.z;
        float rw = (v[i].w - mu) * inv * wv.w + bv.w;
        *(bf162*)(orow + c)     = __floats2bfloat162_rn(rx, ry);
        *(bf162*)(orow + c + 2) = __floats2bfloat162_rn(rz, rw);
    }
}

// ---------------- bf16 tensor-core GEMM (3-stage cp.async) ----------------
#define GBM 128
#define GBN 128
#define GBK 32

template <int EPI, typename CT>
__global__ void __launch_bounds__(256) bgemm_kernel(
    const bf16* __restrict__ A, const bf16* __restrict__ B,
    const float* __restrict__ bias, CT* __restrict__ C,
    int M, int N, int K,
    const float* __restrict__ res, const float* __restrict__ gamma)
{
    __shared__ bf16 As[3][GBM][GBK + 8];
    __shared__ bf16 Bs[3][GBK][GBN + 8];

    int tid  = threadIdx.x;
    int lane = tid & 31;
    int warp = tid >> 5;
    int wm = warp >> 2;
    int wn = warp & 3;
    int row0 = blockIdx.y * GBM;
    int col0 = blockIdx.x * GBN;

    const bf16* Ab = A + (size_t)row0 * K;
    const bf16* Bb = B + col0;

    int a_r[2], a_c[2], b_r[2], b_c[2];
#pragma unroll
    for (int i = 0; i < 2; i++) {
        int ch = tid * 2 + i;
        a_r[i] = ch >> 2;  a_c[i] = (ch & 3) * 8;
        b_r[i] = ch >> 4;  b_c[i] = (ch & 15) * 8;
    }

    float acc[4][4][4];
#pragma unroll
    for (int mi = 0; mi < 4; mi++)
#pragma unroll
        for (int ni = 0; ni < 4; ni++)
#pragma unroll
            for (int r = 0; r < 4; r++) acc[mi][ni][r] = 0.f;

    int nk = K / GBK;
    // prologue: stages 0, 1
#pragma unroll
    for (int s = 0; s < 2; s++) {
        int k0 = s * GBK;
#pragma unroll
        for (int i = 0; i < 2; i++) {
            CP_ASYNC16(sptr(&As[s][a_r[i]][a_c[i]]), Ab + (size_t)a_r[i] * K + k0 + a_c[i]);
        }
#pragma unroll
        for (int i = 0; i < 2; i++) {
            CP_ASYNC16(sptr(&Bs[s][b_r[i]][b_c[i]]), Bb + (size_t)(k0 + b_r[i]) * N + b_c[i]);
        }
        asm volatile("cp.async.commit_group;\n" ::: "memory");
    }

    int buf = 0, nbuf = 2;
    for (int kt = 0; kt < nk; kt++) {
        asm volatile("cp.async.wait_group 1;\n" ::: "memory");
        __syncthreads();
        if (kt + 2 < nk) {
            int k0 = (kt + 2) * GBK;
#pragma unroll
            for (int i = 0; i < 2; i++) {
                CP_ASYNC16(sptr(&As[nbuf][a_r[i]][a_c[i]]), Ab + (size_t)a_r[i] * K + k0 + a_c[i]);
            }
#pragma unroll
            for (int i = 0; i < 2; i++) {
                CP_ASYNC16(sptr(&Bs[nbuf][b_r[i]][b_c[i]]), Bb + (size_t)(k0 + b_r[i]) * N + b_c[i]);
            }
        }
        asm volatile("cp.async.commit_group;\n" ::: "memory");  // (possibly empty) keeps group count in sync

#pragma unroll
        for (int kk = 0; kk < 2; kk++) {
            unsigned a[4][4], b[4][2];
#pragma unroll
            for (int mi = 0; mi < 4; mi++) {
                unsigned addr = sptr(&As[buf][wm * 64 + mi * 16 + (lane & 15)][kk * 16 + (lane >> 4) * 8]);
                asm volatile("ldmatrix.sync.aligned.m8n8.x4.shared.b16 {%0,%1,%2,%3},[%4];"
                    : "=r"(a[mi][0]), "=r"(a[mi][1]), "=r"(a[mi][2]), "=r"(a[mi][3])
                    : "r"(addr));
            }
#pragma unroll
            for (int ni = 0; ni < 4; ni++) {
                unsigned addr = sptr(&Bs[buf][kk * 16 + (lane & 15)][wn * 32 + ni * 8]);
                asm volatile("ldmatrix.sync.aligned.m8n8.x2.trans.shared.b16 {%0,%1},[%2];"
                    : "=r"(b[ni][0]), "=r"(b[ni][1]) : "r"(addr));
            }
#pragma unroll
            for (int mi = 0; mi < 4; mi++)
#pragma unroll
                for (int ni = 0; ni < 4; ni++)
                    asm volatile("mma.sync.aligned.m16n8k16.row.col.f32.bf16.bf16.f32 "
                        "{%0,%1,%2,%3},{%4,%5,%6,%7},{%8,%9},{%0,%1,%2,%3};"
                        : "+f"(acc[mi][ni][0]), "+f"(acc[mi][ni][1]),
                          "+f"(acc[mi][ni][2]), "+f"(acc[mi][ni][3])
                        : "r"(a[mi][0]), "r"(a[mi][1]), "r"(a[mi][2]), "r"(a[mi][3]),
                          "r"(b[ni][0]), "r"(b[ni][1]));
        }
        buf = (buf + 1) % 3;
        nbuf = (nbuf + 1) % 3;
    }

    int lr = lane >> 2;
    int lc = (lane & 3) * 2;
#pragma unroll
    for (int mi = 0; mi < 4; mi++) {
#pragma unroll
        for (int half = 0; half < 2; half++) {
            int grow = row0 + wm * 64 + mi * 16 + lr + half * 8;
#pragma unroll
            for (int ni = 0; ni < 4; ni++) {
                int gcol = col0 + wn * 32 + ni * 8 + lc;
                float v0 = acc[mi][ni][half * 2 + 0] + bias[gcol];
                float v1 = acc[mi][ni][half * 2 + 1] + bias[gcol + 1];
                if (EPI == 1) {
                    v0 = 0.5f * v0 * (1.f + erff(v0 * 0.70710678118f));
                    v1 = 0.5f * v1 * (1.f + erff(v1 * 0.70710678118f));
                }
                if (EPI == 2) {
                    const float* rp = res + (size_t)grow * N + gcol;
                    v0 = rp[0] + gamma[gcol] * v0;
                    v1 = rp[1] + gamma[gcol + 1] * v1;
                }
                if (sizeof(CT) == 4) {
                    float* cp = (float*)C + (size_t)grow * N + gcol;
                    cp[0] = v0; cp[1] = v1;
                } else {
                    bf16* cp = (bf16*)C + (size_t)grow * N + gcol;
                    *(bf162*)cp = __floats2bfloat162_rn(v0, v1);
                }
            }
        }
    }
}

// ---------------- tensor-core attention ------------------------------------
// block = (window, head-pair): 4 warps, warp = (head in pair, row half)
__global__ void __launch_bounds__(128) attn_mma_kernel(
    const bf16* __restrict__ qkv, const float* __restrict__ rel_table,
    bf16* __restrict__ out)
{
    __shared__ bf16 qs[64][72], ks[64][72], vs[64][72];
    __shared__ float tbl[2][225];
    __shared__ int rg[64];

    int w    = blockIdx.x;
    int hb   = blockIdx.y;          // 0..7 head pair
    int tid  = threadIdx.x;
    int lane = tid & 31;
    int warp = tid >> 5;
    int hh   = warp >> 1;           // head within pair
    int wr   = warp & 1;            // row half (32 rows)

    for (int i = tid; i < 2 * 225; i += 128) {
        int h2 = i / 225, idx = i - h2 * 225;
        tbl[h2][idx] = rel_table[idx * HEADS + hb * 2 + h2];
    }
    if (tid < 64) {
        int hbw = w >> 5, wbw = w & 31;
        int ii = hbw * 8 + (tid >> 3);
        int jj = wbw * 8 + (tid & 7);
        int rh = (ii < 248) ? 0 : (ii < 252 ? 1 : 2);
        int rw = (jj < 248) ? 0 : (jj < 252 ? 1 : 2);
        rg[tid] = rh * 3 + rw;
    }

    // async load q/k/v: 64 rows x 64 cols bf16 each
    const bf16* base = qkv + (size_t)w * 64 * (3 * HDIM) + hb * 64;
    for (int ch = tid; ch < 512; ch += 128) {
        int r = ch >> 3, c = (ch & 7) * 8;
        const bf16* rp = base + (size_t)r * (3 * HDIM);
        CP_ASYNC16(sptr(&qs[r][c]), rp + c);
        CP_ASYNC16(sptr(&ks[r][c]), rp + HDIM + c);
        CP_ASYNC16(sptr(&vs[r][c]), rp + 2 * HDIM + c);
    }
    asm volatile("cp.async.commit_group;\n" ::: "memory");
    asm volatile("cp.async.wait_group 0;\n" ::: "memory");
    __syncthreads();

    int co = hh * 32;               // head's column offset in smem

    // ---- S = Q @ K^T  (32 rows x 64 cols per warp) ----
    float sacc[2][8][4];
#pragma unroll
    for (int mi = 0; mi < 2; mi++)
#pragma unroll
        for (int ni = 0; ni < 8; ni++)
#pragma unroll
            for (int r = 0; r < 4; r++) sacc[mi][ni][r] = 0.f;

#pragma unroll
    for (int kk = 0; kk < 2; kk++) {
        int k0 = co + kk * 16;
        unsigned af[2][4];
#pragma unroll
        for (int mi = 0; mi < 2; mi++) {
            unsigned addr = sptr(&qs[wr * 32 + mi * 16 + (lane & 15)][k0 + (lane >> 4) * 8]);
            asm volatile("ldmatrix.sync.aligned.m8n8.x4.shared.b16 {%0,%1,%2,%3},[%4];"
                : "=r"(af[mi][0]), "=r"(af[mi][1]), "=r"(af[mi][2]), "=r"(af[mi][3])
                : "r"(addr));
        }
        unsigned bf[8][2];
#pragma unroll
        for (int ni = 0; ni < 8; ni++) {
            // K is [n][k] row-major -> NON-trans ldmatrix gives col fragment
            unsigned addr = sptr(&ks[ni * 8 + (lane & 7)][k0 + ((lane >> 3) & 1) * 8]);
            asm volatile("ldmatrix.sync.aligned.m8n8.x2.shared.b16 {%0,%1},[%2];"
                : "=r"(bf[ni][0]), "=r"(bf[ni][1]) : "r"(addr));
        }
#pragma unroll
        for (int mi = 0; mi < 2; mi++)
#pragma unroll
            for (int ni = 0; ni < 8; ni++)
                asm volatile("mma.sync.aligned.m16n8k16.row.col.f32.bf16.bf16.f32 "
                    "{%0,%1,%2,%3},{%4,%5,%6,%7},{%8,%9},{%0,%1,%2,%3};"
                    : "+f"(sacc[mi][ni][0]), "+f"(sacc[mi][ni][1]),
                      "+f"(sacc[mi][ni][2]), "+f"(sacc[mi][ni][3])
                    : "r"(af[mi][0]), "r"(af[mi][1]), "r"(af[mi][2]), "r"(af[mi][3]),
                      "r"(bf[ni][0]), "r"(bf[ni][1]));
    }

    // ---- bias + mask + softmax on fragments ----
    const float scale = 0.17677669529663687f;
    int lq  = lane >> 2;
    int lc2 = (lane & 3) * 2;
#pragma unroll
    for (int mi = 0; mi < 2; mi++) {
#pragma unroll
        for (int hf = 0; hf < 2; hf++) {
            int l = wr * 32 + mi * 16 + hf * 8 + lq;
            int il = l >> 3, jl = l & 7;
            int rgl = rg[l];
            float mx = -1e30f;
#pragma unroll
            for (int ni = 0; ni < 8; ni++) {
#pragma unroll
                for (int j = 0; j < 2; j++) {
                    int m = ni * 8 + lc2 + j;
                    int im = m >> 3, jm = m & 7;
                    float v = sacc[mi][ni][hf * 2 + j] * scale
                            + tbl[hh][(il - im + 7) * 15 + (jl - jm + 7)];
                    if (rg[m] != rgl) v = -1e30f;
                    sacc[mi][ni][hf * 2 + j] = v;
                    mx = fmaxf(mx, v);
                }
            }
            mx = fmaxf(mx, __shfl_xor_sync(0xffffffffu, mx, 1));
            mx = fmaxf(mx, __shfl_xor_sync(0xffffffffu, mx, 2));
            float sum = 0.f;
#pragma unroll
            for (int ni = 0; ni < 8; ni++) {
#pragma unroll
                for (int j = 0; j < 2; j++) {
                    float e = __expf(sacc[mi][ni][hf * 2 + j] - mx);
                    sacc[mi][ni][hf * 2 + j] = e;
                    sum += e;
                }
            }
            sum += __shfl_xor_sync(0xffffffffu, sum, 1);
            sum += __shfl_xor_sync(0xffffffffu, sum, 2);
            float inv = 1.f / sum;
#pragma unroll
            for (int ni = 0; ni < 8; ni++) {
                sacc[mi][ni][hf * 2 + 0] *= inv;
                sacc[mi][ni][hf * 2 + 1] *= inv;
            }
        }
    }

    // ---- convert P to bf16 A fragments ----
    unsigned pfr[2][4][4];
#pragma unroll
    for (int mi = 0; mi < 2; mi++)
#pragma unroll
        for (int q = 0; q < 4; q++) {
            pfr[mi][q][0] = packbf(sacc[mi][2 * q][0],     sacc[mi][2 * q][1]);
            pfr[mi][q][1] = packbf(sacc[mi][2 * q][2],     sacc[mi][2 * q][3]);
            pfr[mi][q][2] = packbf(sacc[mi][2 * q + 1][0], sacc[mi][2 * q + 1][1]);
            pfr[mi][q][3] = packbf(sacc[mi][2 * q + 1][2], sacc[mi][2 * q + 1][3]);
        }

    // ---- O = P @ V ----
    float oacc[2][4][4];
#pragma unroll
    for (int mi = 0; mi < 2; mi++)
#pragma unroll
        for (int nj = 0; nj < 4; nj++)
#pragma unroll
            for (int r = 0; r < 4; r++) oacc[mi][nj][r] = 0.f;

#pragma unroll
    for (int q = 0; q < 4; q++) {
        unsigned bv[4][2];
#pragma unroll
        for (int nj = 0; nj < 4; nj++) {
            unsigned addr = sptr(&vs[q * 16 + (lane & 15)][co + nj * 8]);
            asm volatile("ldmatrix.sync.aligned.m8n8.x2.trans.shared.b16 {%0,%1},[%2];"
                : "=r"(bv[nj][0]), "=r"(bv[nj][1]) : "r"(addr));
        }
#pragma unroll
        for (int mi = 0; mi < 2; mi++)
#pragma unroll
            for (int nj = 0; nj < 4; nj++)
                asm volatile("mma.sync.aligned.m16n8k16.row.col.f32.bf16.bf16.f32 "
                    "{%0,%1,%2,%3},{%4,%5,%6,%7},{%8,%9},{%0,%1,%2,%3};"
                    : "+f"(oacc[mi][nj][0]), "+f"(oacc[mi][nj][1]),
                      "+f"(oacc[mi][nj][2]), "+f"(oacc[mi][nj][3])
                    : "r"(pfr[mi][q][0]), "r"(pfr[mi][q][1]), "r"(pfr[mi][q][2]), "r"(pfr[mi][q][3]),
                      "r"(bv[nj][0]), "r"(bv[nj][1]));
    }

    // ---- store ----
    int hgl = hb * 2 + hh;
#pragma unroll
    for (int mi = 0; mi < 2; mi++)
#pragma unroll
        for (int hf = 0; hf < 2; hf++) {
            int l = wr * 32 + mi * 16 + hf * 8 + lq;
            bf16* op = out + (size_t)(w * 64 + l) * HDIM + hgl * 32 + lc2;
#pragma unroll
            for (int nj = 0; nj < 4; nj++)
                *(bf162*)(op + nj * 8) =
                    __floats2bfloat162_rn(oacc[mi][nj][hf * 2 + 0], oacc[mi][nj][hf * 2 + 1]);
        }
}

// ---------------- launch -----------------------------------------------------
extern "C" void kernel_launch(void* const* d_in, const int* in_sizes, int n_in,
                              void* d_out, int out_size)
{
    (void)in_sizes; (void)n_in; (void)out_size;
    const float* x     = (const float*)d_in[0];
    const float* n1w   = (const float*)d_in[1];
    const float* n1b   = (const float*)d_in[2];
    const float* qkvw  = (const float*)d_in[3];
    const float* qkvb  = (const float*)d_in[4];
    const float* projw = (const float*)d_in[5];
    const float* projb = (const float*)d_in[6];
    const float* relt  = (const float*)d_in[7];
    const float* g1    = (const float*)d_in[8];
    const float* n2w   = (const float*)d_in[9];
    const float* n2b   = (const float*)d_in[10];
    const float* fc1w  = (const float*)d_in[11];
    const float* fc1b  = (const float*)d_in[12];
    const float* fc2w  = (const float*)d_in[13];
    const float* fc2b  = (const float*)d_in[14];
    const float* g2    = (const float*)d_in[15];
    float* out = (float*)d_out;

    float *p_win, *p_o1;
    bf16 *p_xnb, *p_qkvb, *p_attb, *p_hb, *p_wq, *p_wp, *p_w1, *p_w2;
    cudaGetSymbolAddress((void**)&p_win,  g_win);
    cudaGetSymbolAddress((void**)&p_o1,   g_o1);
    cudaGetSymbolAddress((void**)&p_xnb,  g_xnb);
    cudaGetSymbolAddress((void**)&p_qkvb, g_qkvb);
    cudaGetSymbolAddress((void**)&p_attb, g_attb);
    cudaGetSymbolAddress((void**)&p_hb,   g_hb);
    cudaGetSymbolAddress((void**)&p_wq,   g_wq);
    cudaGetSymbolAddress((void**)&p_wp,   g_wp);
    cudaGetSymbolAddress((void**)&p_w1,   g_w1);
    cudaGetSymbolAddress((void**)&p_w2,   g_w2);

    f2bf_kernel<<<(HDIM * 3 * HDIM / 4 + 255) / 256, 256>>>(qkvw, p_wq, HDIM * 3 * HDIM / 4);
    f2bf_kernel<<<(HDIM * HDIM / 4 + 255) / 256, 256>>>(projw, p_wp, HDIM * HDIM / 4);
    f2bf_kernel<<<(HDIM * 4 * HDIM / 4 + 255) / 256, 256>>>(fc1w, p_w1, HDIM * 4 * HDIM / 4);
    f2bf_kernel<<<(4 * HDIM * HDIM / 4 + 255) / 256, 256>>>(fc2w, p_w2, 4 * HDIM * HDIM / 4);

    dim3 tp(32, 8);
    partition_kernel<<<dim3(NTOK / 32, HDIM / 32), tp>>>(x, p_win);
    ln_kernel<<<NTOK / 8, 256>>>(p_win, p_xnb, n1w, n1b);
    bgemm_kernel<0, bf16><<<dim3(3 * HDIM / GBN, NTOK / GBM), 256>>>(
        p_xnb, p_wq, qkvb, p_qkvb, NTOK, 3 * HDIM, HDIM, nullptr, nullptr);
    attn_mma_kernel<<<dim3(NW, 8), 128>>>(p_qkvb, relt, p_attb);
    bgemm_kernel<2, float><<<dim3(HDIM / GBN, NTOK / GBM), 256>>>(
        p_attb, p_wp, projb, p_o1, NTOK, HDIM, HDIM, p_win, g1);
    ln_kernel<<<NTOK / 8, 256>>>(p_o1, p_xnb, n2w, n2b);
    bgemm_kernel<1, bf16><<<dim3(4 * HDIM / GBN, NTOK / GBM), 256>>>(
        p_xnb, p_w1, fc1b, p_hb, NTOK, 4 * HDIM, HDIM, nullptr, nullptr);
    bgemm_kernel<2, float><<<dim3(HDIM / GBN, NTOK / GBM), 256>>>(
        p_hb, p_w2, fc2b, p_win, NTOK, HDIM, 4 * HDIM, p_o1, g2);
    reverse_kernel<<<dim3(NTOK / 32, HDIM / 32), tp>>>(p_win, out);
}